// round 12
// baseline (speedup 1.0000x reference)
#include <cuda_runtime.h>
#include <cuda_bf16.h>
#include <math.h>
#include <stdint.h>

#define N_NODES 8192
#define N_EDGE  512
#define DIM     1024
#define HIDD    1024

// output float offsets: (edges, H, dots)
#define E_OFF 0
#define H_OFF (N_EDGE * DIM)                 // 524288
#define DOTS_OFF (H_OFF + N_NODES * N_EDGE)  // 4718592

// ==================== small helpers ====================
__device__ __forceinline__ uint32_t smem_u32(const void* p) {
    uint32_t a;
    asm("{ .reg .u64 t; cvta.to.shared.u64 t, %1; cvt.u32.u64 %0, t; }" : "=r"(a) : "l"(p));
    return a;
}
__device__ __forceinline__ void cp16(uint32_t dst, const void* src) {
    asm volatile("cp.async.cg.shared.global [%0], [%1], 16;" :: "r"(dst), "l"(src));
}
#define CP_COMMIT() asm volatile("cp.async.commit_group;" ::: "memory")
#define CP_WAIT0()  asm volatile("cp.async.wait_group 0;" ::: "memory")
#define CP_WAIT1()  asm volatile("cp.async.wait_group 1;" ::: "memory")

__device__ __forceinline__ void ldsm_x4(uint32_t* r, uint32_t addr) {
    asm volatile("ldmatrix.sync.aligned.m8n8.x4.shared.b16 {%0,%1,%2,%3}, [%4];"
                 : "=r"(r[0]), "=r"(r[1]), "=r"(r[2]), "=r"(r[3]) : "r"(addr));
}
__device__ __forceinline__ void mma_bf16(float* c, const uint32_t* a, const uint32_t* b) {
    asm volatile("mma.sync.aligned.m16n8k16.row.col.f32.bf16.bf16.f32 "
                 "{%0,%1,%2,%3}, {%4,%5,%6,%7}, {%8,%9}, {%0,%1,%2,%3};"
                 : "+f"(c[0]), "+f"(c[1]), "+f"(c[2]), "+f"(c[3])
                 : "r"(a[0]), "r"(a[1]), "r"(a[2]), "r"(a[3]), "r"(b[0]), "r"(b[1]));
}

// 3-way split: v = h + m + l  (8+8+8 mantissa bits; ensures full fp32 coverage)
__device__ __forceinline__ void split3(float v, __nv_bfloat16& h, __nv_bfloat16& m, __nv_bfloat16& l) {
    h = __float2bfloat16_rn(v);
    float r1 = v - __bfloat162float(h);
    m = __float2bfloat16_rn(r1);
    l = __float2bfloat16_rn(r1 - __bfloat162float(m));
}
__device__ __forceinline__ unsigned fkey(float f) {
    unsigned u = __float_as_uint(f);
    return u ^ (((int)u >> 31) | 0x80000000u);
}

// ==================== scratch (static device memory) ====================
__device__ __nv_bfloat16 g_xh [N_NODES * DIM], g_xm [N_NODES * DIM], g_xl [N_NODES * DIM];
__device__ __nv_bfloat16 g_kh [N_NODES * DIM], g_km [N_NODES * DIM], g_kl [N_NODES * DIM];
__device__ __nv_bfloat16 g_q2h[N_NODES * DIM], g_q2m[N_NODES * DIM], g_q2l[N_NODES * DIM];
__device__ float         g_vf [N_NODES * DIM];
__device__ float         g_dv [N_NODES * N_EDGE];
__device__ __nv_bfloat16 g_e0h[N_EDGE * DIM], g_e0m[N_EDGE * DIM], g_e0l[N_EDGE * DIM];
__device__ __nv_bfloat16 g_qh [N_EDGE * DIM], g_qm [N_EDGE * DIM], g_ql [N_EDGE * DIM];
__device__ __nv_bfloat16 g_cth[N_EDGE * 2 * DIM], g_ctm[N_EDGE * 2 * DIM], g_ctl[N_EDGE * 2 * DIM];
__device__ __nv_bfloat16 g_h1h[N_EDGE * HIDD], g_h1m[N_EDGE * HIDD], g_h1l[N_EDGE * HIDD];
__device__ __nv_bfloat16 g_eh [N_EDGE * DIM], g_em [N_EDGE * DIM], g_el [N_EDGE * DIM];
__device__ __nv_bfloat16 g_k2h[N_EDGE * DIM], g_k2m[N_EDGE * DIM], g_k2l[N_EDGE * DIM];
// transposed weights (bf16 triple): T[N][K]
__device__ __nv_bfloat16 g_WqTh[DIM * DIM], g_WqTm[DIM * DIM], g_WqTl[DIM * DIM];
__device__ __nv_bfloat16 g_WkTh[DIM * DIM], g_WkTm[DIM * DIM], g_WkTl[DIM * DIM];
__device__ __nv_bfloat16 g_WvTh[DIM * DIM], g_WvTm[DIM * DIM], g_WvTl[DIM * DIM];
__device__ __nv_bfloat16 g_W1Th[HIDD * 2 * DIM], g_W1Tm[HIDD * 2 * DIM], g_W1Tl[HIDD * 2 * DIM];
__device__ __nv_bfloat16 g_W2Th[DIM * HIDD], g_W2Tm[DIM * HIDD], g_W2Tl[DIM * HIDD];

// ==================== reductions ====================
__device__ __forceinline__ float blockReduceSum(float val, float* shm) {
    int lane = threadIdx.x & 31, wid = threadIdx.x >> 5;
    #pragma unroll
    for (int o = 16; o > 0; o >>= 1) val += __shfl_down_sync(0xffffffffu, val, o);
    if (lane == 0) shm[wid] = val;
    __syncthreads();
    int nw = (blockDim.x + 31) >> 5;
    val = (threadIdx.x < nw) ? shm[threadIdx.x] : 0.f;
    if (wid == 0) {
        #pragma unroll
        for (int o = 16; o > 0; o >>= 1) val += __shfl_down_sync(0xffffffffu, val, o);
        if (lane == 0) shm[0] = val;
    }
    __syncthreads();
    float r = shm[0];
    __syncthreads();
    return r;
}
__device__ __forceinline__ float blockReduceMax(float val, float* shm) {
    int lane = threadIdx.x & 31, wid = threadIdx.x >> 5;
    #pragma unroll
    for (int o = 16; o > 0; o >>= 1) val = fmaxf(val, __shfl_down_sync(0xffffffffu, val, o));
    if (lane == 0) shm[wid] = val;
    __syncthreads();
    int nw = (blockDim.x + 31) >> 5;
    val = (threadIdx.x < nw) ? shm[threadIdx.x] : -INFINITY;
    if (wid == 0) {
        #pragma unroll
        for (int o = 16; o > 0; o >>= 1) val = fmaxf(val, __shfl_down_sync(0xffffffffu, val, o));
        if (lane == 0) shm[0] = val;
    }
    __syncthreads();
    float r = shm[0];
    __syncthreads();
    return r;
}
__device__ __forceinline__ unsigned blockReduceSumU(unsigned val, unsigned* shm) {
    int lane = threadIdx.x & 31, wid = threadIdx.x >> 5;
    #pragma unroll
    for (int o = 16; o > 0; o >>= 1) val += __shfl_down_sync(0xffffffffu, val, o);
    if (lane == 0) shm[wid] = val;
    __syncthreads();
    int nw = (blockDim.x + 31) >> 5;
    val = (threadIdx.x < nw) ? shm[threadIdx.x] : 0u;
    if (wid == 0) {
        #pragma unroll
        for (int o = 16; o > 0; o >>= 1) val += __shfl_down_sync(0xffffffffu, val, o);
        if (lane == 0) shm[0] = val;
    }
    __syncthreads();
    unsigned r = shm[0];
    __syncthreads();
    return r;
}

// ==================== layernorm -> bf16 triple ====================
__global__ __launch_bounds__(256) void ln_kernel(
    const float* __restrict__ in, const float* __restrict__ g, const float* __restrict__ b,
    __nv_bfloat16* __restrict__ oh, __nv_bfloat16* __restrict__ om, __nv_bfloat16* __restrict__ ol)
{
    __shared__ float shm[32];
    int row = blockIdx.x;
    const float* x = in + (size_t)row * DIM;
    float s = 0.f, s2 = 0.f;
    for (int i = threadIdx.x; i < DIM; i += blockDim.x) { float v = x[i]; s += v; s2 += v * v; }
    float S  = blockReduceSum(s,  shm);
    float S2 = blockReduceSum(s2, shm);
    float mean = S / DIM;
    float var  = S2 / DIM - mean * mean;
    float inv  = rsqrtf(var + 1e-5f);
    for (int i = threadIdx.x; i < DIM; i += blockDim.x) {
        float y = (x[i] - mean) * inv * g[i] + b[i];
        __nv_bfloat16 h, m, l; split3(y, h, m, l);
        size_t o = (size_t)row * DIM + i;
        oh[o] = h; om[o] = m; ol[o] = l;
    }
}

__global__ __launch_bounds__(256) void edge_ln_kernel(
    const float* __restrict__ noise, const float* __restrict__ mu, const float* __restrict__ ls,
    const float* __restrict__ g, const float* __restrict__ b,
    __nv_bfloat16* __restrict__ e0h, __nv_bfloat16* __restrict__ e0m, __nv_bfloat16* __restrict__ e0l,
    __nv_bfloat16* __restrict__ cth, __nv_bfloat16* __restrict__ ctm, __nv_bfloat16* __restrict__ ctl)
{
    __shared__ float shm[32];
    int row = blockIdx.x;
    const float* nz = noise + (size_t)row * DIM;
    float s = 0.f, s2 = 0.f;
    for (int i = threadIdx.x; i < DIM; i += blockDim.x) {
        float v = mu[i] + expf(ls[i]) * nz[i];
        s += v; s2 += v * v;
    }
    float S  = blockReduceSum(s,  shm);
    float S2 = blockReduceSum(s2, shm);
    float mean = S / DIM;
    float var  = S2 / DIM - mean * mean;
    float inv  = rsqrtf(var + 1e-5f);
    for (int i = threadIdx.x; i < DIM; i += blockDim.x) {
        float v = mu[i] + expf(ls[i]) * nz[i];
        float y = (v - mean) * inv * g[i] + b[i];
        __nv_bfloat16 h, m, l; split3(y, h, m, l);
        size_t o = (size_t)row * DIM + i;
        e0h[o] = h; e0m[o] = m; e0l[o] = l;
        size_t oc = (size_t)row * 2 * DIM + i;
        cth[oc] = h; ctm[oc] = m; ctl[oc] = l;
    }
}

// ==================== fused weight transposes: T[N][K] = W[K][N] (elementwise-identical) ====
struct TJob {
    const float* W;
    __nv_bfloat16 *Th, *Tm, *Tl;
    int R, C, start;
};

__global__ __launch_bounds__(256) void transpose_all(TJob j0, TJob j1, TJob j2, TJob j3, TJob j4)
{
    __shared__ float t[32][33];
    int tb = blockIdx.x;
    TJob j;
    if      (tb >= j4.start) j = j4;
    else if (tb >= j3.start) j = j3;
    else if (tb >= j2.start) j = j2;
    else if (tb >= j1.start) j = j1;
    else                     j = j0;
    int rel = tb - j.start;
    int tilesPerRow = j.C / 32;
    int c0 = (rel % tilesPerRow) * 32;
    int r0 = (rel / tilesPerRow) * 32;

    #pragma unroll
    for (int i = threadIdx.y; i < 32; i += 8)
        t[i][threadIdx.x] = j.W[(size_t)(r0 + i) * j.C + c0 + threadIdx.x];
    __syncthreads();
    #pragma unroll
    for (int i = threadIdx.y; i < 32; i += 8) {
        float v = t[threadIdx.x][i];   // W[r0+tx][c0+i]
        __nv_bfloat16 h, m, l; split3(v, h, m, l);
        size_t o = (size_t)(c0 + i) * j.R + r0 + threadIdx.x;
        j.Th[o] = h; j.Tm[o] = m; j.Tl[o] = l;
    }
}

// ==================== 6-term split HMMA GEMM with RN chunk-flush (R7 numerics, verbatim) ==
// Chunk accumulators start at 0 each BK-chunk (limits tensor-core RZ accumulation error);
// master accumulation happens in fp32 FADD (round-to-nearest).
#define BK 32
#define PADK 40            // BK + 8 elems -> 80B row stride, conflict-free ldmatrix

template<int TBM, int TBN, int TWM, int TWN>
__device__ __forceinline__ void gemm6_body(
    const __nv_bfloat16* __restrict__ Ah, const __nv_bfloat16* __restrict__ Am, const __nv_bfloat16* __restrict__ Al,
    const __nv_bfloat16* __restrict__ Bh, const __nv_bfloat16* __restrict__ Bm, const __nv_bfloat16* __restrict__ Bl,
    const float* __restrict__ bias, float alpha, int relu,
    float* __restrict__ Cf,
    __nv_bfloat16* __restrict__ Ch, __nv_bfloat16* __restrict__ Cm, __nv_bfloat16* __restrict__ Cl,
    int M, int N, int K, char* smem)
{
    constexpr int WMC  = TBM / TWM;          // warps along M
    constexpr int MI   = TWM / 16;
    constexpr int NJ   = TWN / 8;
    constexpr int NJ2  = TWN / 16;
    constexpr int TILEA = TBM * PADK * 2;
    constexpr int TILEB = TBN * PADK * 2;
    constexpr int STAGE = 3 * (TILEA + TILEB);

    const uint32_t sb = smem_u32(smem);
    const int tid = threadIdx.x;
    const int lane = tid & 31, wid = tid >> 5;
    const int warp_m = wid % WMC, warp_n = wid / WMC;
    const int bm = blockIdx.y * TBM, bn = blockIdx.x * TBN;

    float master[MI][NJ][4];
    #pragma unroll
    for (int i = 0; i < MI; i++)
        #pragma unroll
        for (int j = 0; j < NJ; j++)
            #pragma unroll
            for (int t = 0; t < 4; t++) master[i][j][t] = 0.f;

    const int NC = K / BK;

    auto issue_load = [&](int kc, int stage) {
        uint32_t base = sb + stage * STAGE;
        const __nv_bfloat16* as[3] = {Ah, Am, Al};
        const __nv_bfloat16* bs[3] = {Bh, Bm, Bl};
        #pragma unroll
        for (int t = 0; t < 3; t++) {
            for (int id = tid; id < TBM * 4; id += 256) {
                int row = id >> 2, c = id & 3;
                uint32_t so = (uint32_t)(row * (PADK * 2) + c * 16);
                cp16(base + t * TILEA + so, as[t] + (size_t)(bm + row) * K + (size_t)kc * BK + c * 8);
            }
            for (int id = tid; id < TBN * 4; id += 256) {
                int row = id >> 2, c = id & 3;
                uint32_t so = (uint32_t)(row * (PADK * 2) + c * 16);
                cp16(base + 3 * TILEA + t * TILEB + so, bs[t] + (size_t)(bn + row) * K + (size_t)kc * BK + c * 8);
            }
        }
    };

    issue_load(0, 0);
    CP_COMMIT();

    const int arow = lane & 15;
    const int acol8 = lane >> 4;
    const int bg = lane >> 3, br = lane & 7;
    const int bnrow = ((bg & 2) ? 8 : 0) + br;
    const int bkoff = (bg & 1) ? 8 : 0;

    for (int kc = 0; kc < NC; kc++) {
        if (kc + 1 < NC) {
            issue_load(kc + 1, (kc + 1) & 1);
            CP_COMMIT();
            CP_WAIT1();
        } else {
            CP_WAIT0();
        }
        __syncthreads();

        uint32_t base = sb + (kc & 1) * STAGE;
        uint32_t sAh = base, sAm = base + TILEA, sAl = base + 2 * TILEA;
        uint32_t sBh = base + 3 * TILEA, sBm = sBh + TILEB, sBl = sBh + 2 * TILEB;

        // fresh chunk accumulator (tensor-core RZ chain limited to this chunk)
        float chunk[MI][NJ][4];
        #pragma unroll
        for (int i = 0; i < MI; i++)
            #pragma unroll
            for (int j = 0; j < NJ; j++)
                #pragma unroll
                for (int t = 0; t < 4; t++) chunk[i][j][t] = 0.f;

        #pragma unroll
        for (int ks = 0; ks < 2; ks++) {
            int k0 = ks * 16;
            uint32_t ah[MI][4], am[MI][4], al[MI][4];
            #pragma unroll
            for (int mi = 0; mi < MI; mi++) {
                uint32_t roff = (uint32_t)((warp_m * TWM + mi * 16 + arow) * (PADK * 2)
                                           + (k0 + acol8 * 8) * 2);
                ldsm_x4(ah[mi], sAh + roff);
                ldsm_x4(am[mi], sAm + roff);
                ldsm_x4(al[mi], sAl + roff);
            }
            uint32_t bh[NJ][2], bmm[NJ][2], bl[NJ][2];
            #pragma unroll
            for (int nj2 = 0; nj2 < NJ2; nj2++) {
                uint32_t roff = (uint32_t)((warp_n * TWN + nj2 * 16 + bnrow) * (PADK * 2)
                                           + (k0 + bkoff) * 2);
                uint32_t r4[4];
                ldsm_x4(r4, sBh + roff);
                bh[nj2 * 2][0] = r4[0]; bh[nj2 * 2][1] = r4[1];
                bh[nj2 * 2 + 1][0] = r4[2]; bh[nj2 * 2 + 1][1] = r4[3];
                ldsm_x4(r4, sBm + roff);
                bmm[nj2 * 2][0] = r4[0]; bmm[nj2 * 2][1] = r4[1];
                bmm[nj2 * 2 + 1][0] = r4[2]; bmm[nj2 * 2 + 1][1] = r4[3];
                ldsm_x4(r4, sBl + roff);
                bl[nj2 * 2][0] = r4[0]; bl[nj2 * 2][1] = r4[1];
                bl[nj2 * 2 + 1][0] = r4[2]; bl[nj2 * 2 + 1][1] = r4[3];
            }
            #pragma unroll
            for (int mi = 0; mi < MI; mi++) {
                #pragma unroll
                for (int nj = 0; nj < NJ; nj++) {
                    mma_bf16(chunk[mi][nj], ah[mi], bh[nj]);   // hh
                    mma_bf16(chunk[mi][nj], ah[mi], bmm[nj]);  // hm
                    mma_bf16(chunk[mi][nj], am[mi], bh[nj]);   // mh
                    mma_bf16(chunk[mi][nj], ah[mi], bl[nj]);   // hl
                    mma_bf16(chunk[mi][nj], al[mi], bh[nj]);   // lh
                    mma_bf16(chunk[mi][nj], am[mi], bmm[nj]);  // mm
                }
            }
        }
        // RN flush to master (FFMA pipe, round-to-nearest)
        #pragma unroll
        for (int i = 0; i < MI; i++)
            #pragma unroll
            for (int j = 0; j < NJ; j++)
                #pragma unroll
                for (int t = 0; t < 4; t++) master[i][j][t] += chunk[i][j][t];
        __syncthreads();
    }

    // ---- epilogue (R7 source, verbatim) ----
    int gid = lane >> 2, qid = lane & 3;
    #pragma unroll
    for (int mi = 0; mi < MI; mi++) {
        #pragma unroll
        for (int nj = 0; nj < NJ; nj++) {
            int n0 = bn + warp_n * TWN + nj * 8 + qid * 2;
            float bv0 = bias ? bias[n0] : 0.f;
            float bv1 = bias ? bias[n0 + 1] : 0.f;
            #pragma unroll
            for (int half = 0; half < 2; half++) {
                int mrow = bm + warp_m * TWM + mi * 16 + gid + half * 8;
                float v0 = master[mi][nj][half * 2 + 0] * alpha + bv0;
                float v1 = master[mi][nj][half * 2 + 1] * alpha + bv1;
                if (relu) { v0 = fmaxf(v0, 0.f); v1 = fmaxf(v1, 0.f); }
                size_t o = (size_t)mrow * N + n0;
                if (Cf) *(float2*)(Cf + o) = make_float2(v0, v1);
                if (Ch) {
                    __nv_bfloat16 h0, m0, l0, h1, m1, l1;
                    split3(v0, h0, m0, l0);
                    split3(v1, h1, m1, l1);
                    __nv_bfloat162 hp; hp.x = h0; hp.y = h1;
                    __nv_bfloat162 mp; mp.x = m0; mp.y = m1;
                    __nv_bfloat162 lp; lp.x = l0; lp.y = l1;
                    *(__nv_bfloat162*)(Ch + o) = hp;
                    *(__nv_bfloat162*)(Cm + o) = mp;
                    *(__nv_bfloat162*)(Cl + o) = lp;
                }
            }
        }
    }
}

template<int TBM, int TBN, int TWM, int TWN>
__global__ __launch_bounds__(256) void gemm6(
    const __nv_bfloat16* __restrict__ Ah, const __nv_bfloat16* __restrict__ Am, const __nv_bfloat16* __restrict__ Al,
    const __nv_bfloat16* __restrict__ Bh, const __nv_bfloat16* __restrict__ Bm, const __nv_bfloat16* __restrict__ Bl,
    const float* __restrict__ bias, float alpha, int relu,
    float* __restrict__ Cf,
    __nv_bfloat16* __restrict__ Ch, __nv_bfloat16* __restrict__ Cm, __nv_bfloat16* __restrict__ Cl,
    int M, int N, int K)
{
    extern __shared__ char smem[];
    gemm6_body<TBM, TBN, TWM, TWN>(Ah, Am, Al, Bh, Bm, Bl, bias, alpha, relu,
                                   Cf, Ch, Cm, Cl, M, N, K, smem);
}

// batched variant: 3 jobs sharing the same A (k / v / q2); same body -> same per-tile math
struct GJob {
    const __nv_bfloat16 *Bh, *Bm, *Bl;
    const float* bias;
    float* Cf;
    __nv_bfloat16 *Ch, *Cm, *Cl;
    int relu;
};

template<int TBM, int TBN, int TWM, int TWN>
__global__ __launch_bounds__(256) void gemm6_b3(
    const __nv_bfloat16* __restrict__ Ah, const __nv_bfloat16* __restrict__ Am, const __nv_bfloat16* __restrict__ Al,
    GJob j0, GJob j1, GJob j2, int M, int N, int K)
{
    extern __shared__ char smem[];
    GJob j = (blockIdx.z == 0) ? j0 : ((blockIdx.z == 1) ? j1 : j2);
    gemm6_body<TBM, TBN, TWM, TWN>(Ah, Am, Al, j.Bh, j.Bm, j.Bl, j.bias, 1.f, j.relu,
                                   j.Cf, j.Ch, j.Cm, j.Cl, M, N, K, smem);
}

// ==================== attn row: softmax+eps+renorm, top-k, sparse update ====================
__global__ __launch_bounds__(256) void attn_update_kernel(
    const float* __restrict__ dots, const float* __restrict__ v,
    const int* __restrict__ kn_ptr,
    __nv_bfloat16* __restrict__ cth, __nv_bfloat16* __restrict__ ctm, __nv_bfloat16* __restrict__ ctl)
{
    __shared__ float sval[N_NODES];
    __shared__ float shmf[32];
    __shared__ unsigned shmu[32];
    __shared__ int   sel_idx[128];
    __shared__ float sel_w[128];
    __shared__ unsigned scount, stie;

    int row = blockIdx.x;
    int k = kn_ptr[0];
    if (k > 128) k = 128;
    const float* dr = dots + (size_t)row * N_NODES;

    for (int i = threadIdx.x; i < N_NODES; i += blockDim.x) sval[i] = dr[i];
    __syncthreads();

    float m = -INFINITY;
    for (int i = threadIdx.x; i < N_NODES; i += blockDim.x) m = fmaxf(m, sval[i]);
    float rowmax = blockReduceMax(m, shmf);
    float s = 0.f;
    for (int i = threadIdx.x; i < N_NODES; i += blockDim.x) s += expf(sval[i] - rowmax);
    float sumexp = blockReduceSum(s, shmf);
    float invsum = 1.f / sumexp;

    unsigned lo = 0u, hi = 0xFFFFFFFFu;
    while (lo < hi) {
        unsigned mid = lo + ((hi - lo) >> 1) + ((hi - lo) & 1u);
        unsigned c = 0;
        for (int i = threadIdx.x; i < N_NODES; i += blockDim.x)
            if (fkey(sval[i]) >= mid) c++;
        c = blockReduceSumU(c, shmu);
        if (c >= (unsigned)k) lo = mid; else hi = mid - 1u;
    }
    unsigned Tth = lo;

    if (threadIdx.x == 0) scount = 0u;
    __syncthreads();
    for (int i = threadIdx.x; i < N_NODES; i += blockDim.x) {
        if (fkey(sval[i]) > Tth) {
            unsigned p = atomicAdd(&scount, 1u);
            if (p < (unsigned)k) sel_idx[p] = i;
        }
    }
    __syncthreads();
    if (threadIdx.x == 0) stie = scount;
    __syncthreads();
    for (int i = threadIdx.x; i < N_NODES; i += blockDim.x) {
        if (fkey(sval[i]) == Tth) {
            unsigned p = atomicAdd(&stie, 1u);
            if (p < (unsigned)k) sel_idx[p] = i;
        }
    }
    __syncthreads();

    float renorm = 1.f / (1.f + (float)N_NODES * 1e-8f);
    for (int sI = threadIdx.x; sI < k; sI += blockDim.x) {
        int idx = sel_idx[sI];
        sel_w[sI] = (expf(sval[idx] - rowmax) * invsum + 1e-8f) * renorm;
    }
    __syncthreads();

    float acc[4] = {0.f, 0.f, 0.f, 0.f};
    for (int sI = 0; sI < k; sI++) {
        int idx = sel_idx[sI];
        float w = sel_w[sI];
        const float* vr = v + (size_t)idx * DIM;
        #pragma unroll
        for (int j = 0; j < 4; j++)
            acc[j] = fmaf(w, __ldg(vr + threadIdx.x + j * 256), acc[j]);
    }
    #pragma unroll
    for (int j = 0; j < 4; j++) {
        __nv_bfloat16 h, mm2, l; split3(acc[j], h, mm2, l);
        size_t o = (size_t)row * 2 * DIM + DIM + threadIdx.x + j * 256;
        cth[o] = h; ctm[o] = mm2; ctl[o] = l;
    }
}

// ==================== H = mask_topk(softmax(dots_v), k_e) (R7 verbatim) ====================
__global__ __launch_bounds__(128) void h_kernel(
    const float* __restrict__ dv, const int* __restrict__ ke_ptr, float* __restrict__ Hout)
{
    __shared__ float sval[N_EDGE];
    __shared__ float shmf[32];
    __shared__ unsigned shmu[32];
    __shared__ unsigned stie;

    int row = blockIdx.x;
    int k = ke_ptr[0];
    if (k > 128) k = 128;
    const float* dr = dv + (size_t)row * N_EDGE;
    for (int i = threadIdx.x; i < N_EDGE; i += blockDim.x) sval[i] = dr[i];
    __syncthreads();

    float m = -INFINITY;
    for (int i = threadIdx.x; i < N_EDGE; i += blockDim.x) m = fmaxf(m, sval[i]);
    float rowmax = blockReduceMax(m, shmf);
    float s = 0.f;
    for (int i = threadIdx.x; i < N_EDGE; i += blockDim.x) s += expf(sval[i] - rowmax);
    float sumexp = blockReduceSum(s, shmf);
    float invsum = 1.f / sumexp;

    unsigned lo = 0u, hi = 0xFFFFFFFFu;
    while (lo < hi) {
        unsigned mid = lo + ((hi - lo) >> 1) + ((hi - lo) & 1u);
        unsigned c = 0;
        for (int i = threadIdx.x; i < N_EDGE; i += blockDim.x)
            if (fkey(sval[i]) >= mid) c++;
        c = blockReduceSumU(c, shmu);
        if (c >= (unsigned)k) lo = mid; else hi = mid - 1u;
    }
    unsigned Tth = lo;

    unsigned cg = 0;
    for (int i = threadIdx.x; i < N_EDGE; i += blockDim.x)
        if (fkey(sval[i]) > Tth) cg++;
    unsigned cnt_gt = blockReduceSumU(cg, shmu);
    unsigned needed = (unsigned)k - cnt_gt;
    if (threadIdx.x == 0) stie = 0u;
    __syncthreads();

    float* hr = Hout + (size_t)row * N_EDGE;
    for (int i = threadIdx.x; i < N_EDGE; i += blockDim.x) {
        unsigned ky = fkey(sval[i]);
        bool sel = false;
        if (ky > Tth) sel = true;
        else if (ky == Tth) {
            unsigned p = atomicAdd(&stie, 1u);
            sel = (p < needed);
        }
        hr[i] = sel ? expf(sval[i] - rowmax) * invsum : 0.f;
    }
}

// ==================== launch ====================
#define SMEM_BIG   (2 * 3 * (64 * PADK * 2 + 128 * PADK * 2))   // 92160
#define SMEM_SMALL (2 * 3 * (32 * PADK * 2 + 128 * PADK * 2))   // 76800

extern "C" void kernel_launch(void* const* d_in, const int* in_sizes, int n_in,
                              void* d_out, int out_size)
{
    const float* inputs  = (const float*)d_in[0];
    const float* noise   = (const float*)d_in[1];
    const float* emu     = (const float*)d_in[2];
    const float* elogsig = (const float*)d_in[3];
    const float* Wq = (const float*)d_in[4];  const float* bq = (const float*)d_in[5];
    const float* Wk = (const float*)d_in[6];  const float* bk = (const float*)d_in[7];
    const float* Wv = (const float*)d_in[8];  const float* bv = (const float*)d_in[9];
    const float* W1 = (const float*)d_in[10]; const float* b1 = (const float*)d_in[11];
    const float* W2 = (const float*)d_in[12]; const float* b2 = (const float*)d_in[13];
    const float* gin = (const float*)d_in[14]; const float* bin = (const float*)d_in[15];
    const float* ge  = (const float*)d_in[16]; const float* be  = (const float*)d_in[17];
    const int* kn = (const int*)d_in[18];
    const int* ke = (const int*)d_in[19];

    float* out = (float*)d_out;
    float* out_edges = out + E_OFF;
    float* out_H     = out + H_OFF;
    float* out_dots  = out + DOTS_OFF;

    auto big    = gemm6<64, 128, 32, 32>;
    auto big3   = gemm6_b3<64, 128, 32, 32>;
    auto small  = gemm6<32, 128, 16, 32>;
    cudaFuncSetAttribute(big,   cudaFuncAttributeMaxDynamicSharedMemorySize, SMEM_BIG);
    cudaFuncSetAttribute(big3,  cudaFuncAttributeMaxDynamicSharedMemorySize, SMEM_BIG);
    cudaFuncSetAttribute(small, cudaFuncAttributeMaxDynamicSharedMemorySize, SMEM_SMALL);

    __nv_bfloat16 *xh, *xm, *xl, *kh, *km, *kl, *q2h, *q2m, *q2l;
    __nv_bfloat16 *e0h, *e0m, *e0l, *qh, *qm, *ql, *cth, *ctm, *ctl;
    __nv_bfloat16 *h1h, *h1m, *h1l, *eh, *em, *el, *k2h, *k2m, *k2l;
    __nv_bfloat16 *wqh, *wqm, *wql, *wkh, *wkm, *wkl, *wvh, *wvm, *wvl;
    __nv_bfloat16 *w1h, *w1m, *w1l, *w2h, *w2m, *w2l;
    float *vf, *dv;
    cudaGetSymbolAddress((void**)&xh, g_xh);   cudaGetSymbolAddress((void**)&xm, g_xm);   cudaGetSymbolAddress((void**)&xl, g_xl);
    cudaGetSymbolAddress((void**)&kh, g_kh);   cudaGetSymbolAddress((void**)&km, g_km);   cudaGetSymbolAddress((void**)&kl, g_kl);
    cudaGetSymbolAddress((void**)&q2h, g_q2h); cudaGetSymbolAddress((void**)&q2m, g_q2m); cudaGetSymbolAddress((void**)&q2l, g_q2l);
    cudaGetSymbolAddress((void**)&vf,  g_vf);  cudaGetSymbolAddress((void**)&dv, g_dv);
    cudaGetSymbolAddress((void**)&e0h, g_e0h); cudaGetSymbolAddress((void**)&e0m, g_e0m); cudaGetSymbolAddress((void**)&e0l, g_e0l);
    cudaGetSymbolAddress((void**)&qh, g_qh);   cudaGetSymbolAddress((void**)&qm, g_qm);   cudaGetSymbolAddress((void**)&ql, g_ql);
    cudaGetSymbolAddress((void**)&cth, g_cth); cudaGetSymbolAddress((void**)&ctm, g_ctm); cudaGetSymbolAddress((void**)&ctl, g_ctl);
    cudaGetSymbolAddress((void**)&h1h, g_h1h); cudaGetSymbolAddress((void**)&h1m, g_h1m); cudaGetSymbolAddress((void**)&h1l, g_h1l);
    cudaGetSymbolAddress((void**)&eh, g_eh);   cudaGetSymbolAddress((void**)&em, g_em);   cudaGetSymbolAddress((void**)&el, g_el);
    cudaGetSymbolAddress((void**)&k2h, g_k2h); cudaGetSymbolAddress((void**)&k2m, g_k2m); cudaGetSymbolAddress((void**)&k2l, g_k2l);
    cudaGetSymbolAddress((void**)&wqh, g_WqTh); cudaGetSymbolAddress((void**)&wqm, g_WqTm); cudaGetSymbolAddress((void**)&wql, g_WqTl);
    cudaGetSymbolAddress((void**)&wkh, g_WkTh); cudaGetSymbolAddress((void**)&wkm, g_WkTm); cudaGetSymbolAddress((void**)&wkl, g_WkTl);
    cudaGetSymbolAddress((void**)&wvh, g_WvTh); cudaGetSymbolAddress((void**)&wvm, g_WvTm); cudaGetSymbolAddress((void**)&wvl, g_WvTl);
    cudaGetSymbolAddress((void**)&w1h, g_W1Th); cudaGetSymbolAddress((void**)&w1m, g_W1Tm); cudaGetSymbolAddress((void**)&w1l, g_W1Tl);
    cudaGetSymbolAddress((void**)&w2h, g_W2Th); cudaGetSymbolAddress((void**)&w2m, g_W2Tm); cudaGetSymbolAddress((void**)&w2l, g_W2Tl);

    const float scale = 1.0f / 32.0f;  // 1024^-0.5
    dim3 tb(32, 8);

    // fused weight transposes (one launch; elementwise-identical to 5 separate launches)
    {
        TJob j0 = {Wq, wqh, wqm, wql, DIM, DIM, 0};
        TJob j1 = {Wk, wkh, wkm, wkl, DIM, DIM, 1024};
        TJob j2 = {Wv, wvh, wvm, wvl, DIM, DIM, 2048};
        TJob j3 = {W1, w1h, w1m, w1l, 2 * DIM, HIDD, 3072};
        TJob j4 = {W2, w2h, w2m, w2l, HIDD, DIM, 5120};
        transpose_all<<<6144, tb>>>(j0, j1, j2, j3, j4);
    }

    // layernorms
    ln_kernel<<<N_NODES, 256>>>(inputs, gin, bin, xh, xm, xl);
    edge_ln_kernel<<<N_EDGE, 256>>>(noise, emu, elogsig, ge, be, e0h, e0m, e0l, cth, ctm, ctl);

    // k / v / q2 fused into one launch (shared A = x); same body => same per-tile bits
    {
        GJob jk = {wkh, wkm, wkl, bk, nullptr, kh, km, kl, 1};
        GJob jv = {wvh, wvm, wvl, bv, vf, nullptr, nullptr, nullptr, 1};
        GJob jq = {wqh, wqm, wql, bq, nullptr, q2h, q2m, q2l, 0};
        big3<<<dim3(DIM / 128, N_NODES / 64, 3), 256, SMEM_BIG>>>(
            xh, xm, xl, jk, jv, jq, N_NODES, DIM, DIM);
    }
    // q = relu(e0@Wq+bq) -> triple
    small<<<dim3(DIM / 128, N_EDGE / 32), 256, SMEM_SMALL>>>(
        e0h, e0m, e0l, wqh, wqm, wql, bq, 1.f, 1, nullptr, qh, qm, ql, N_EDGE, DIM, DIM);
    // dots = scale * q@k^T -> fp32 (output)
    big<<<dim3(N_NODES / 128, N_EDGE / 64), 256, SMEM_BIG>>>(
        qh, qm, ql, kh, km, kl, nullptr, scale, 0, out_dots, nullptr, nullptr, nullptr, N_EDGE, N_NODES, DIM);
    // sparse top-k attention -> cat second half (triple)
    attn_update_kernel<<<N_EDGE, 256>>>(out_dots, vf, kn, cth, ctm, ctl);
    // h1 = relu(cat@W1+b1) -> triple
    small<<<dim3(HIDD / 128, N_EDGE / 32), 256, SMEM_SMALL>>>(
        cth, ctm, ctl, w1h, w1m, w1l, b1, 1.f, 1, nullptr, h1h, h1m, h1l, N_EDGE, HIDD, 2 * DIM);
    // edges = h1@W2+b2 -> fp32 output + triple
    small<<<dim3(DIM / 128, N_EDGE / 32), 256, SMEM_SMALL>>>(
        h1h, h1m, h1l, w2h, w2m, w2l, b2, 1.f, 0, out_edges, eh, em, el, N_EDGE, DIM, HIDD);
    // k2 = relu(edges@Wk+bk) -> triple
    small<<<dim3(DIM / 128, N_EDGE / 32), 256, SMEM_SMALL>>>(
        eh, em, el, wkh, wkm, wkl, bk, 1.f, 1, nullptr, k2h, k2m, k2l, N_EDGE, DIM, DIM);
    // dots_v = scale * q2@k2^T -> fp32
    big<<<dim3(N_EDGE / 128, N_NODES / 64), 256, SMEM_BIG>>>(
        q2h, q2m, q2l, k2h, k2m, k2l, nullptr, scale, 0, dv, nullptr, nullptr, nullptr, N_NODES, N_EDGE, DIM);
    // H
    h_kernel<<<N_NODES, 128>>>(dv, ke, out_H);
}